// round 16
// baseline (speedup 1.0000x reference)
#include <cuda_runtime.h>
#include <math.h>

#define BDIM 16
#define CO   64
#define RN   16            // Chebyshev nodes
#define CC   72            // padded channels: [0..63]=co, [64]=density, [65..71]=pad
#define RDIM 128
#define NBLK 256
#define NTHR 512
#define NCH  16            // n-chunks (N/128)

// ---------------- device globals ----------------
__device__ unsigned g_lo_u, g_hi_u;
__device__ int g_bar_cnt;
__device__ volatile int g_bar_gen;
__device__ int g_cntA[BDIM];                                    // per-batch phase-2 done count
__device__ int g_cntWB[BDIM];                                   // per-batch phase-3 done count
__device__ __align__(16) float g_Apart[BDIM * NCH * RN * CC];   // per-chunk partials
__device__ __align__(16) float g_Btd[BDIM * RN];
__device__ __align__(16) float g_WB[BDIM * RN * RDIM];

__device__ __forceinline__ unsigned f2ord(float f) {
    unsigned u = __float_as_uint(f);
    return (u & 0x80000000u) ? ~u : (u | 0x80000000u);
}
__device__ __forceinline__ float ord2f(unsigned u) {
    return (u & 0x80000000u) ? __uint_as_float(u ^ 0x80000000u) : __uint_as_float(~u);
}

__device__ __forceinline__ void grid_barrier() {
    __syncthreads();
    if (threadIdx.x == 0) {
        __threadfence();
        int gen = g_bar_gen;
        if (atomicAdd(&g_bar_cnt, 1) == NBLK - 1) {
            atomicExch(&g_bar_cnt, 0);
            __threadfence();
            g_bar_gen = gen + 1;
        } else {
            while (g_bar_gen == gen) { __nanosleep(64); }
        }
        __threadfence();
    }
    __syncthreads();
}

// group signal: all threads fence, then one signals (one-shot counter)
__device__ __forceinline__ void group_signal(int* cnt) {
    __threadfence();
    __syncthreads();
    if (threadIdx.x == 0) atomicAdd(cnt, 1);
}
// group wait: spin until all NCH producers of this batch have signaled
__device__ __forceinline__ void group_wait(int* cnt) {
    if (threadIdx.x == 0) {
        while (atomicAdd(cnt, 0) < NCH) { __nanosleep(32); }
    }
    __syncthreads();
}

// ---------------- smem layout (floats) ----------------
#define P_S   0
#define P_W   RN                 // 16
#define P_K   (2 * RN)           // 32, K: 256
#define P_MSC (P_K + RN * RN)    // 288
#define SCR   292                // scratch base (1168 B, 16B aligned)
// phase 2: Ltn[128][20]=2560 @SCR, co_s[128][17 fl4]=8704 @SCR+2560 (reduce overlay on co_s)
// phase 3: As[1152] @SCR, Bt[1152] @SCR+1152, Ws[520] @SCR+2304
// phase 4: Lat0[16][132]=2112 @SCR, Lat1 @SCR+2112, WBs[2048] @SCR+4224,
//          dens[256] @SCR+6272, Btd[16] @SCR+6528, W0s[128] @SCR+6544, bi[128] @SCR+6672
#define SM_FLOATS (SCR + 11264)

__global__ void __launch_bounds__(NTHR, 2)
k_all(const float* __restrict__ ci, const float* __restrict__ co,
      const float* __restrict__ ti, const float* __restrict__ ls,
      const float* __restrict__ W, const float* __restrict__ bias,
      float* __restrict__ out, int N, int M)
{
    extern __shared__ float sm[];
    const int tid = threadIdx.x, bid = blockIdx.x;
    const int bb = bid >> 4, chunk = bid & 15, n0 = chunk * 128;

    // ================= phase 0: global min/max + co_s prefetch =================
    {
        const int nci = N * BDIM;
        const int total = nci + M * BDIM;
        float lo = 3.4e38f, hi = -3.4e38f;
        for (int i = bid * NTHR + tid; i < total; i += NBLK * NTHR) {
            float v = (i < nci) ? ci[i] : ti[i - nci];
            lo = fminf(lo, v);
            hi = fmaxf(hi, v);
        }
        #pragma unroll
        for (int o = 16; o; o >>= 1) {
            lo = fminf(lo, __shfl_xor_sync(0xFFFFFFFFu, lo, o));
            hi = fmaxf(hi, __shfl_xor_sync(0xFFFFFFFFu, hi, o));
        }
        if ((tid & 31) == 0) {
            atomicMin(&g_lo_u, f2ord(lo));
            atomicMax(&g_hi_u, f2ord(hi));
        }
        // prefetch co tile for phase 2
        float4* co_s4 = (float4*)(sm + SCR + 2560);
        for (int i = tid; i < 128 * 17; i += NTHR) {
            int nn = i / 17, c4 = i - nn * 17;
            float4 v = (c4 < 16)
                ? ((const float4*)(co + ((size_t)(n0 + nn) * BDIM + bb) * CO))[c4]
                : make_float4(1.f, 0.f, 0.f, 0.f);
            co_s4[i] = v;
        }
    }
    grid_barrier();

    // ================= phase 1: per-block setup =================
    {
        if (tid == 0) {
            float l = ls[0];
            sm[P_MSC + 0] = -0.5f / (l * l);
            sm[P_MSC + 1] = ord2f(__ldcg(&g_lo_u));
            sm[P_MSC + 2] = ord2f(__ldcg(&g_hi_u));
        }
        __syncthreads();
        if (tid < RN) {
            float lo = sm[P_MSC + 1], hi = sm[P_MSC + 2];
            float c = 0.5f * (lo + hi);
            float h = 0.5f * (hi - lo) * 1.0002f + 1e-5f;
            double ang = (double)tid * M_PI / (double)(RN - 1);
            sm[P_S + tid] = c + h * (float)cos(ang);
            float wj = ((tid == 0) || (tid == RN - 1)) ? 0.5f : 1.0f;
            sm[P_W + tid] = (tid & 1) ? -wj : wj;
        }
        __syncthreads();
        float a = sm[P_MSC + 0];
        for (int i = tid; i < RN * RN; i += NTHR) {
            float d = sm[P_S + (i >> 4)] - sm[P_S + (i & 15)];
            sm[P_K + i] = expf(a * d * d);
        }
        __syncthreads();
    }

    // ================= phase 2: stage A — 4 n-slices x (4q x 4c) tiles =================
    {
        float* Ltn  = sm + SCR;             // [128][20], pre-normalized
        float* co_s = sm + SCR + 2560;      // [128][17 fl4]

        if (tid < 128) {
            float x = ci[(n0 + tid) * BDIM + bb];
            float den = 0.0f;
            float* lr = Ltn + tid * 20;
            #pragma unroll
            for (int j = 0; j < RN; ++j) {
                float d = x - sm[P_S + j];
                if (d == 0.0f) d = 1e-30f;
                float r = __fdividef(sm[P_W + j], d);
                den += r;
                lr[j] = r;
            }
            float inv = __fdividef(1.0f, den);
            #pragma unroll
            for (int j = 0; j < RN; ++j) lr[j] *= inv;
        }
        __syncthreads();

        const bool act = (tid < 272);       // 4 slices x 68 tiles
        int slice = 0, qg = 0, cg = 0;
        float acc[4][4];
        #pragma unroll
        for (int qi = 0; qi < 4; ++qi)
            #pragma unroll
            for (int ci4 = 0; ci4 < 4; ++ci4) acc[qi][ci4] = 0.0f;

        if (act) {
            slice = tid / 68;
            int rem = tid - slice * 68;
            qg = rem / 17; cg = rem - qg * 17;
            const float4* Lt4 = (const float4*)Ltn;
            const float4* co4 = (const float4*)co_s;
            const int nb = slice * 32;
            #pragma unroll 4
            for (int i = 0; i < 32; ++i) {
                int n = nb + i;
                float4 lt = Lt4[n * 5 + qg];
                float4 cv = co4[n * 17 + cg];
                float lq[4] = {lt.x, lt.y, lt.z, lt.w};
                #pragma unroll
                for (int qi = 0; qi < 4; ++qi) {
                    acc[qi][0] = fmaf(lq[qi], cv.x, acc[qi][0]);
                    acc[qi][1] = fmaf(lq[qi], cv.y, acc[qi][1]);
                    acc[qi][2] = fmaf(lq[qi], cv.z, acc[qi][2]);
                    acc[qi][3] = fmaf(lq[qi], cv.w, acc[qi][3]);
                }
            }
        }
        __syncthreads();

        float4* red = (float4*)(sm + SCR + 2560);   // overlay on co_s
        if (act && slice > 0) {
            int rem = tid - slice * 68;
            #pragma unroll
            for (int qi = 0; qi < 4; ++qi)
                red[((slice - 1) * 68 + rem) * 4 + qi] =
                    make_float4(acc[qi][0], acc[qi][1], acc[qi][2], acc[qi][3]);
        }
        __syncthreads();

        if (tid < 68) {
            #pragma unroll
            for (int s = 0; s < 3; ++s)
                #pragma unroll
                for (int qi = 0; qi < 4; ++qi) {
                    float4 v = red[(s * 68 + tid) * 4 + qi];
                    acc[qi][0] += v.x; acc[qi][1] += v.y;
                    acc[qi][2] += v.z; acc[qi][3] += v.w;
                }
            const int q0 = qg * 4, c0 = cg * 4;
            #pragma unroll
            for (int qi = 0; qi < 4; ++qi) {
                float4* ap = (float4*)(g_Apart +
                    (((size_t)bb * NCH + chunk) * RN + q0 + qi) * CC + c0);
                *ap = make_float4(acc[qi][0], acc[qi][1], acc[qi][2], acc[qi][3]);
            }
        }
    }
    group_signal(&g_cntA[bb]);
    group_wait(&g_cntA[bb]);

    // ================= phase 3: stage B (chunk-sum; Bt = K*A ; WB slice) =================
    {
        float* As = sm + SCR;
        float* Bt = sm + SCR + 1152;
        float* Ws = sm + SCR + 2304;
        const int r0 = chunk * 8;

        for (int i = tid; i < RN * CC / 4; i += NTHR) {
            const float4* base = (const float4*)(g_Apart + (size_t)bb * NCH * RN * CC) + i;
            float4 s = make_float4(0.f, 0.f, 0.f, 0.f);
            #pragma unroll
            for (int ch = 0; ch < NCH; ++ch) {
                float4 v = __ldcg(base + ch * (RN * CC / 4));
                s.x += v.x; s.y += v.y; s.z += v.z; s.w += v.w;
            }
            ((float4*)As)[i] = s;
        }
        for (int i = tid; i < 8 * 65; i += NTHR)
            Ws[i] = W[r0 * 65 + i];
        __syncthreads();

        for (int i = tid; i < RN * CC; i += NTHR) {
            int p = i / CC, c = i - p * CC;
            float acc = 0.0f;
            #pragma unroll
            for (int qq = 0; qq < RN; ++qq)
                acc = fmaf(sm[P_K + p * RN + qq], As[qq * CC + c], acc);
            Bt[i] = acc;
            if (c == 64 && r0 == 0) g_Btd[bb * RN + p] = acc;
        }
        __syncthreads();

        for (int i = tid; i < RN * 8; i += NTHR) {
            int p = i >> 3, rr = i & 7;
            float acc = 0.0f;
            #pragma unroll 8
            for (int c = 0; c < 64; ++c)
                acc = fmaf(Ws[rr * 65 + (c + 1)], Bt[p * CC + c], acc);
            g_WB[((size_t)bb * RN + p) * RDIM + r0 + rr] = acc;
        }
    }
    group_signal(&g_cntWB[bb]);
    group_wait(&g_cntWB[bb]);

    // ================= phase 4: stage C — 2 same-b tiles, one setup =================
    float* Lat0 = sm + SCR;                 // [16][132]
    float* Lat1 = sm + SCR + 2112;          // [16][132]
    float* WBs  = sm + SCR + 4224;          // 2048
    float* dens = sm + SCR + 6272;          // 256 (both tiles)
    float* Btd  = sm + SCR + 6528;
    float* W0s  = sm + SCR + 6544;
    float* bi_s = sm + SCR + 6672;

    const int w = tid >> 5, l = tid & 31;
    const int mw0 = w * 8;
    const int tile0 = 2 * bid;              // tiles 2*bid, 2*bid+1 share b (= bb)
    const int m00 = (tile0 & 31) * 128;     // tile1 m-base = m00 + 128

    for (int i = tid; i < RN * RDIM / 4; i += NTHR)
        ((float4*)WBs)[i] = __ldcg(((const float4*)(g_WB + (size_t)bb * RN * RDIM)) + i);
    if (tid < RN) Btd[tid] = __ldcg(&g_Btd[bb * RN + tid]);
    if (tid < 128) {
        W0s[tid]  = W[tid * 65];
        bi_s[tid] = bias[tid];
    }
    __syncthreads();

    // barycentric for BOTH tiles at once (256 active threads)
    if (tid < 256) {
        const int t = tid >> 7, mm = tid & 127;
        float* LatT = t ? Lat1 : Lat0;
        float x = ti[(m00 + t * 128 + mm) * BDIM + bb];
        float den = 0.0f;
        #pragma unroll
        for (int j = 0; j < RN; ++j) {
            float d = x - sm[P_S + j];
            if (d == 0.0f) d = 1e-30f;
            float r = __fdividef(sm[P_W + j], d);
            den += r;
            LatT[j * 132 + mm] = r;
        }
        float inv = __fdividef(1.0f, den);
        float dm = 0.0f;
        #pragma unroll
        for (int j = 0; j < RN; ++j) {
            float v = LatT[j * 132 + mm] * inv;
            LatT[j * 132 + mm] = v;
            dm = fmaf(v, Btd[j], dm);
        }
        dens[t * 128 + mm] = dm;
    }
    __syncthreads();

    float4 w04 = ((const float4*)W0s)[l];
    float4 bi4 = ((const float4*)bi_s)[l];
    const float4* WBs4 = (const float4*)WBs;

    #pragma unroll
    for (int t = 0; t < 2; ++t) {
        float* Lat = t ? Lat1 : Lat0;
        const int m0 = m00 + t * 128;

        unsigned long long acc01[8], acc23[8];
        #pragma unroll
        for (int k = 0; k < 8; ++k) { acc01[k] = 0ull; acc23[k] = 0ull; }

        #pragma unroll 4
        for (int p = 0; p < RN; ++p) {
            float4 wv = WBs4[p * 32 + l];                 // conflict-free 512B/warp
            unsigned long long wv01, wv23;
            asm("mov.b64 %0, {%1,%2};" : "=l"(wv01) : "f"(wv.x), "f"(wv.y));
            asm("mov.b64 %0, {%1,%2};" : "=l"(wv23) : "f"(wv.z), "f"(wv.w));
            const float4* lmp = (const float4*)(Lat + p * 132 + mw0);   // broadcast
            float4 lma = lmp[0], lmb = lmp[1];
            float lm[8] = {lma.x, lma.y, lma.z, lma.w, lmb.x, lmb.y, lmb.z, lmb.w};
            #pragma unroll
            for (int k = 0; k < 8; ++k) {
                unsigned long long lm2;
                asm("mov.b64 %0, {%1,%1};" : "=l"(lm2) : "f"(lm[k]));
                asm("fma.rn.f32x2 %0, %1, %2, %0;" : "+l"(acc01[k]) : "l"(lm2), "l"(wv01));
                asm("fma.rn.f32x2 %0, %1, %2, %0;" : "+l"(acc23[k]) : "l"(lm2), "l"(wv23));
            }
        }

        #pragma unroll
        for (int k = 0; k < 8; ++k) {
            float dm = dens[t * 128 + mw0 + k];
            float inv = __fdividef(1.0f, dm + 1e-8f);
            float a0, a1, a2, a3;
            asm("mov.b64 {%0,%1}, %2;" : "=f"(a0), "=f"(a1) : "l"(acc01[k]));
            asm("mov.b64 {%0,%1}, %2;" : "=f"(a2), "=f"(a3) : "l"(acc23[k]));
            float4 o;
            o.x = fmaf(a0, inv, fmaf(w04.x, dm, bi4.x));
            o.y = fmaf(a1, inv, fmaf(w04.y, dm, bi4.y));
            o.z = fmaf(a2, inv, fmaf(w04.z, dm, bi4.z));
            o.w = fmaf(a3, inv, fmaf(w04.w, dm, bi4.w));
            ((float4*)(out + ((size_t)(m0 + mw0 + k) * BDIM + bb) * RDIM))[l] = o;
        }
    }
}

// ---------------- launch ----------------
extern "C" void kernel_launch(void* const* d_in, const int* in_sizes, int n_in,
                              void* d_out, int out_size)
{
    const float* ci   = (const float*)d_in[0];
    const float* co   = (const float*)d_in[1];
    const float* ti   = (const float*)d_in[2];
    const float* ls   = (const float*)d_in[3];
    const float* W    = (const float*)d_in[4];
    const float* bias = (const float*)d_in[5];
    float* out = (float*)d_out;

    const int N = in_sizes[0] / BDIM;   // 2048
    const int M = in_sizes[2] / BDIM;   // 4096

    cudaFuncSetAttribute(k_all, cudaFuncAttributeMaxDynamicSharedMemorySize,
                         SM_FLOATS * 4);

    void *p_lo, *p_hi, *p_cnt, *p_gen, *p_cA, *p_cWB;
    cudaGetSymbolAddress(&p_lo,  g_lo_u);
    cudaGetSymbolAddress(&p_hi,  g_hi_u);
    cudaGetSymbolAddress(&p_cnt, (const void*)&g_bar_cnt);
    cudaGetSymbolAddress(&p_gen, (const void*)&g_bar_gen);
    cudaGetSymbolAddress(&p_cA,  g_cntA);
    cudaGetSymbolAddress(&p_cWB, g_cntWB);
    cudaMemsetAsync(p_lo,  0xFF, 4);
    cudaMemsetAsync(p_hi,  0x00, 4);
    cudaMemsetAsync(p_cnt, 0x00, 4);
    cudaMemsetAsync(p_gen, 0x00, 4);
    cudaMemsetAsync(p_cA,  0x00, BDIM * sizeof(int));
    cudaMemsetAsync(p_cWB, 0x00, BDIM * sizeof(int));

    k_all<<<NBLK, NTHR, SM_FLOATS * 4>>>(ci, co, ti, ls, W, bias, out, N, M);
}

// round 17
// speedup vs baseline: 1.0864x; 1.0864x over previous
#include <cuda_runtime.h>
#include <math.h>

#define BDIM 16
#define CO   64
#define RN   16            // Chebyshev nodes
#define CC   72            // padded channels: [0..63]=co, [64]=density, [65..71]=pad
#define RDIM 128
#define NBLK 256
#define NTHR 512
#define NCH  16            // n-chunks (N/128)

// ---------------- device globals ----------------
// g_ctrl layout: [0]=lo_u (memset 0xFF), [1]=hi_u, [2]=bar_cnt, [3]=bar_gen,
//                [4..19]=cntA, [20..35]=cntWB   (all zeroed by one memset)
__device__ __align__(16) unsigned g_ctrl[36];
__device__ __align__(16) float g_Apart[BDIM * NCH * RN * CC];   // per-chunk partials
__device__ __align__(16) float g_Btd[BDIM * RN];
__device__ __align__(16) float g_WB[BDIM * RN * RDIM];

__device__ __forceinline__ unsigned f2ord(float f) {
    unsigned u = __float_as_uint(f);
    return (u & 0x80000000u) ? ~u : (u | 0x80000000u);
}
__device__ __forceinline__ float ord2f(unsigned u) {
    return (u & 0x80000000u) ? __uint_as_float(u ^ 0x80000000u) : __uint_as_float(~u);
}

__device__ __forceinline__ void grid_barrier() {
    __syncthreads();
    if (threadIdx.x == 0) {
        __threadfence();
        volatile int* gen_p = (volatile int*)&g_ctrl[3];
        int gen = *gen_p;
        if (atomicAdd((int*)&g_ctrl[2], 1) == NBLK - 1) {
            atomicExch((int*)&g_ctrl[2], 0);
            __threadfence();
            *gen_p = gen + 1;
        } else {
            while (*gen_p == gen) { __nanosleep(64); }
        }
        __threadfence();
    }
    __syncthreads();
}

// group signal/wait: one-shot per-batch counters
__device__ __forceinline__ void group_signal(int* cnt) {
    __threadfence();
    __syncthreads();
    if (threadIdx.x == 0) atomicAdd(cnt, 1);
}
__device__ __forceinline__ void group_wait(int* cnt) {
    if (threadIdx.x == 0) {
        while (atomicAdd(cnt, 0) < NCH) { __nanosleep(32); }
    }
    __syncthreads();
}

// ---------------- smem layout (floats) ----------------
#define P_S   0
#define P_W   RN                 // 16
#define P_K   (2 * RN)           // 32, K: 256
#define P_MSC (P_K + RN * RN)    // 288
#define SCR   292                // scratch base (1168 B, 16B aligned)
// phase 2: Ltn[128][20]=2560 @SCR, co_s[128][17 fl4]=8704 @SCR+2560 (reduce overlay on co_s)
// phase 3: As[1152] @SCR, Bt[1152] @SCR+1152, Ws[520] @SCR+2304
// phase 4: Lat0[16][132]=2112 @SCR, Lat1 @SCR+2112, WBs[2048] @SCR+4224,
//          dens[256] @SCR+6272, Btd[16] @SCR+6528, W0s[128] @SCR+6544, bi[128] @SCR+6672
#define SM_FLOATS (SCR + 11264)

__global__ void __launch_bounds__(NTHR, 2)
k_all(const float* __restrict__ ci, const float* __restrict__ co,
      const float* __restrict__ ti, const float* __restrict__ ls,
      const float* __restrict__ W, const float* __restrict__ bias,
      float* __restrict__ out, int N, int M)
{
    extern __shared__ float sm[];
    const int tid = threadIdx.x, bid = blockIdx.x;
    const int bb = bid >> 4, chunk = bid & 15, n0 = chunk * 128;

    // ================= phase 0: global min/max + co_s prefetch =================
    {
        const int nci = N * BDIM;
        const int total = nci + M * BDIM;
        float lo = 3.4e38f, hi = -3.4e38f;
        for (int i = bid * NTHR + tid; i < total; i += NBLK * NTHR) {
            float v = (i < nci) ? ci[i] : ti[i - nci];
            lo = fminf(lo, v);
            hi = fmaxf(hi, v);
        }
        #pragma unroll
        for (int o = 16; o; o >>= 1) {
            lo = fminf(lo, __shfl_xor_sync(0xFFFFFFFFu, lo, o));
            hi = fmaxf(hi, __shfl_xor_sync(0xFFFFFFFFu, hi, o));
        }
        if ((tid & 31) == 0) {
            atomicMin(&g_ctrl[0], f2ord(lo));
            atomicMax(&g_ctrl[1], f2ord(hi));
        }
        // prefetch co tile for phase 2
        float4* co_s4 = (float4*)(sm + SCR + 2560);
        for (int i = tid; i < 128 * 17; i += NTHR) {
            int nn = i / 17, c4 = i - nn * 17;
            float4 v = (c4 < 16)
                ? ((const float4*)(co + ((size_t)(n0 + nn) * BDIM + bb) * CO))[c4]
                : make_float4(1.f, 0.f, 0.f, 0.f);
            co_s4[i] = v;
        }
    }
    grid_barrier();

    // ================= phase 1: per-block setup =================
    {
        if (tid == 0) {
            float l = ls[0];
            sm[P_MSC + 0] = -0.5f / (l * l);
            sm[P_MSC + 1] = ord2f(__ldcg(&g_ctrl[0]));
            sm[P_MSC + 2] = ord2f(__ldcg(&g_ctrl[1]));
        }
        __syncthreads();
        if (tid < RN) {
            float lo = sm[P_MSC + 1], hi = sm[P_MSC + 2];
            float c = 0.5f * (lo + hi);
            float h = 0.5f * (hi - lo) * 1.0002f + 1e-5f;
            double ang = (double)tid * M_PI / (double)(RN - 1);
            sm[P_S + tid] = c + h * (float)cos(ang);
            float wj = ((tid == 0) || (tid == RN - 1)) ? 0.5f : 1.0f;
            sm[P_W + tid] = (tid & 1) ? -wj : wj;
        }
        __syncthreads();
        float a = sm[P_MSC + 0];
        for (int i = tid; i < RN * RN; i += NTHR) {
            float d = sm[P_S + (i >> 4)] - sm[P_S + (i & 15)];
            sm[P_K + i] = expf(a * d * d);
        }
        __syncthreads();
    }

    // ================= phase 2: stage A — 4 n-slices x (4q x 4c) tiles =================
    {
        float* Ltn  = sm + SCR;             // [128][20], pre-normalized
        float* co_s = sm + SCR + 2560;      // [128][17 fl4]

        if (tid < 128) {
            float x = ci[(n0 + tid) * BDIM + bb];
            float den = 0.0f;
            float* lr = Ltn + tid * 20;
            #pragma unroll
            for (int j = 0; j < RN; ++j) {
                float d = x - sm[P_S + j];
                if (d == 0.0f) d = 1e-30f;
                float r = __fdividef(sm[P_W + j], d);
                den += r;
                lr[j] = r;
            }
            float inv = __fdividef(1.0f, den);
            #pragma unroll
            for (int j = 0; j < RN; ++j) lr[j] *= inv;
        }
        __syncthreads();

        const bool act = (tid < 272);       // 4 slices x 68 tiles
        int slice = 0, qg = 0, cg = 0;
        float acc[4][4];
        #pragma unroll
        for (int qi = 0; qi < 4; ++qi)
            #pragma unroll
            for (int ci4 = 0; ci4 < 4; ++ci4) acc[qi][ci4] = 0.0f;

        if (act) {
            slice = tid / 68;
            int rem = tid - slice * 68;
            qg = rem / 17; cg = rem - qg * 17;
            const float4* Lt4 = (const float4*)Ltn;
            const float4* co4 = (const float4*)co_s;
            const int nb = slice * 32;
            #pragma unroll 4
            for (int i = 0; i < 32; ++i) {
                int n = nb + i;
                float4 lt = Lt4[n * 5 + qg];
                float4 cv = co4[n * 17 + cg];
                float lq[4] = {lt.x, lt.y, lt.z, lt.w};
                #pragma unroll
                for (int qi = 0; qi < 4; ++qi) {
                    acc[qi][0] = fmaf(lq[qi], cv.x, acc[qi][0]);
                    acc[qi][1] = fmaf(lq[qi], cv.y, acc[qi][1]);
                    acc[qi][2] = fmaf(lq[qi], cv.z, acc[qi][2]);
                    acc[qi][3] = fmaf(lq[qi], cv.w, acc[qi][3]);
                }
            }
        }
        __syncthreads();

        float4* red = (float4*)(sm + SCR + 2560);   // overlay on co_s
        if (act && slice > 0) {
            int rem = tid - slice * 68;
            #pragma unroll
            for (int qi = 0; qi < 4; ++qi)
                red[((slice - 1) * 68 + rem) * 4 + qi] =
                    make_float4(acc[qi][0], acc[qi][1], acc[qi][2], acc[qi][3]);
        }
        __syncthreads();

        if (tid < 68) {
            #pragma unroll
            for (int s = 0; s < 3; ++s)
                #pragma unroll
                for (int qi = 0; qi < 4; ++qi) {
                    float4 v = red[(s * 68 + tid) * 4 + qi];
                    acc[qi][0] += v.x; acc[qi][1] += v.y;
                    acc[qi][2] += v.z; acc[qi][3] += v.w;
                }
            const int q0 = qg * 4, c0 = cg * 4;
            #pragma unroll
            for (int qi = 0; qi < 4; ++qi) {
                float4* ap = (float4*)(g_Apart +
                    (((size_t)bb * NCH + chunk) * RN + q0 + qi) * CC + c0);
                *ap = make_float4(acc[qi][0], acc[qi][1], acc[qi][2], acc[qi][3]);
            }
        }
    }
    group_signal((int*)&g_ctrl[4 + bb]);
    group_wait((int*)&g_ctrl[4 + bb]);

    // ================= phase 3: stage B (chunk-sum; Bt = K*A ; WB slice) =================
    {
        float* As = sm + SCR;
        float* Bt = sm + SCR + 1152;
        float* Ws = sm + SCR + 2304;
        const int r0 = chunk * 8;

        for (int i = tid; i < RN * CC / 4; i += NTHR) {
            const float4* base = (const float4*)(g_Apart + (size_t)bb * NCH * RN * CC) + i;
            float4 s = make_float4(0.f, 0.f, 0.f, 0.f);
            #pragma unroll
            for (int ch = 0; ch < NCH; ++ch) {
                float4 v = __ldcg(base + ch * (RN * CC / 4));
                s.x += v.x; s.y += v.y; s.z += v.z; s.w += v.w;
            }
            ((float4*)As)[i] = s;
        }
        for (int i = tid; i < 8 * 65; i += NTHR)
            Ws[i] = W[r0 * 65 + i];
        __syncthreads();

        for (int i = tid; i < RN * CC; i += NTHR) {
            int p = i / CC, c = i - p * CC;
            float acc = 0.0f;
            #pragma unroll
            for (int qq = 0; qq < RN; ++qq)
                acc = fmaf(sm[P_K + p * RN + qq], As[qq * CC + c], acc);
            Bt[i] = acc;
            if (c == 64 && r0 == 0) g_Btd[bb * RN + p] = acc;
        }
        __syncthreads();

        for (int i = tid; i < RN * 8; i += NTHR) {
            int p = i >> 3, rr = i & 7;
            float acc = 0.0f;
            #pragma unroll 8
            for (int c = 0; c < 64; ++c)
                acc = fmaf(Ws[rr * 65 + (c + 1)], Bt[p * CC + c], acc);
            g_WB[((size_t)bb * RN + p) * RDIM + r0 + rr] = acc;
        }
    }
    group_signal((int*)&g_ctrl[20 + bb]);
    group_wait((int*)&g_ctrl[20 + bb]);

    // ================= phase 4: stage C — 2 same-b tiles, one setup =================
    float* Lat0 = sm + SCR;                 // [16][132]
    float* Lat1 = sm + SCR + 2112;          // [16][132]
    float* WBs  = sm + SCR + 4224;          // 2048
    float* dens = sm + SCR + 6272;          // 256 (both tiles)
    float* Btd  = sm + SCR + 6528;
    float* W0s  = sm + SCR + 6544;
    float* bi_s = sm + SCR + 6672;

    const int w = tid >> 5, l = tid & 31;
    const int mw0 = w * 8;
    const int tile0 = 2 * bid;              // tiles 2*bid, 2*bid+1 share b (= bb)
    const int m00 = (tile0 & 31) * 128;     // tile1 m-base = m00 + 128

    for (int i = tid; i < RN * RDIM / 4; i += NTHR)
        ((float4*)WBs)[i] = __ldcg(((const float4*)(g_WB + (size_t)bb * RN * RDIM)) + i);
    if (tid < RN) Btd[tid] = __ldcg(&g_Btd[bb * RN + tid]);
    if (tid < 128) {
        W0s[tid]  = W[tid * 65];
        bi_s[tid] = bias[tid];
    }
    __syncthreads();

    // barycentric for BOTH tiles at once (256 active threads)
    if (tid < 256) {
        const int t = tid >> 7, mm = tid & 127;
        float* LatT = t ? Lat1 : Lat0;
        float x = ti[(m00 + t * 128 + mm) * BDIM + bb];
        float den = 0.0f;
        #pragma unroll
        for (int j = 0; j < RN; ++j) {
            float d = x - sm[P_S + j];
            if (d == 0.0f) d = 1e-30f;
            float r = __fdividef(sm[P_W + j], d);
            den += r;
            LatT[j * 132 + mm] = r;
        }
        float inv = __fdividef(1.0f, den);
        float dm = 0.0f;
        #pragma unroll
        for (int j = 0; j < RN; ++j) {
            float v = LatT[j * 132 + mm] * inv;
            LatT[j * 132 + mm] = v;
            dm = fmaf(v, Btd[j], dm);
        }
        dens[t * 128 + mm] = dm;
    }
    __syncthreads();

    float4 w04 = ((const float4*)W0s)[l];
    float4 bi4 = ((const float4*)bi_s)[l];
    const float4* WBs4 = (const float4*)WBs;

    #pragma unroll
    for (int t = 0; t < 2; ++t) {
        float* Lat = t ? Lat1 : Lat0;
        const int m0 = m00 + t * 128;

        // m-pair f32x2 accumulation: acc[i][r] = (m=2i, m=2i+1) x wv component r
        unsigned long long acc[4][4];
        #pragma unroll
        for (int i = 0; i < 4; ++i)
            #pragma unroll
            for (int r = 0; r < 4; ++r) acc[i][r] = 0ull;

        #pragma unroll 4
        for (int p = 0; p < RN; ++p) {
            float4 wv = WBs4[p * 32 + l];                 // conflict-free 512B/warp
            unsigned long long wd[4];
            asm("mov.b64 %0, {%1,%1};" : "=l"(wd[0]) : "f"(wv.x));
            asm("mov.b64 %0, {%1,%1};" : "=l"(wd[1]) : "f"(wv.y));
            asm("mov.b64 %0, {%1,%1};" : "=l"(wd[2]) : "f"(wv.z));
            asm("mov.b64 %0, {%1,%1};" : "=l"(wd[3]) : "f"(wv.w));
            // Lat m-pairs loaded directly as u64 lanes (broadcast LDS.128)
            ulonglong2 lp0 = *reinterpret_cast<const ulonglong2*>(Lat + p * 132 + mw0);
            ulonglong2 lp1 = *reinterpret_cast<const ulonglong2*>(Lat + p * 132 + mw0 + 4);
            unsigned long long lm[4] = {lp0.x, lp0.y, lp1.x, lp1.y};
            #pragma unroll
            for (int i = 0; i < 4; ++i) {
                asm("fma.rn.f32x2 %0, %1, %2, %0;" : "+l"(acc[i][0]) : "l"(lm[i]), "l"(wd[0]));
                asm("fma.rn.f32x2 %0, %1, %2, %0;" : "+l"(acc[i][1]) : "l"(lm[i]), "l"(wd[1]));
                asm("fma.rn.f32x2 %0, %1, %2, %0;" : "+l"(acc[i][2]) : "l"(lm[i]), "l"(wd[2]));
                asm("fma.rn.f32x2 %0, %1, %2, %0;" : "+l"(acc[i][3]) : "l"(lm[i]), "l"(wd[3]));
            }
        }

        #pragma unroll
        for (int i = 0; i < 4; ++i) {
            float dmE = dens[t * 128 + mw0 + 2 * i];
            float dmO = dens[t * 128 + mw0 + 2 * i + 1];
            float invE = __fdividef(1.0f, dmE + 1e-8f);
            float invO = __fdividef(1.0f, dmO + 1e-8f);
            float aE[4], aO[4];
            #pragma unroll
            for (int r = 0; r < 4; ++r)
                asm("mov.b64 {%0,%1}, %2;" : "=f"(aE[r]), "=f"(aO[r]) : "l"(acc[i][r]));
            float4 oE, oO;
            oE.x = fmaf(aE[0], invE, fmaf(w04.x, dmE, bi4.x));
            oE.y = fmaf(aE[1], invE, fmaf(w04.y, dmE, bi4.y));
            oE.z = fmaf(aE[2], invE, fmaf(w04.z, dmE, bi4.z));
            oE.w = fmaf(aE[3], invE, fmaf(w04.w, dmE, bi4.w));
            oO.x = fmaf(aO[0], invO, fmaf(w04.x, dmO, bi4.x));
            oO.y = fmaf(aO[1], invO, fmaf(w04.y, dmO, bi4.y));
            oO.z = fmaf(aO[2], invO, fmaf(w04.z, dmO, bi4.z));
            oO.w = fmaf(aO[3], invO, fmaf(w04.w, dmO, bi4.w));
            ((float4*)(out + ((size_t)(m0 + mw0 + 2 * i)     * BDIM + bb) * RDIM))[l] = oE;
            ((float4*)(out + ((size_t)(m0 + mw0 + 2 * i + 1) * BDIM + bb) * RDIM))[l] = oO;
        }
    }
}

// ---------------- launch ----------------
extern "C" void kernel_launch(void* const* d_in, const int* in_sizes, int n_in,
                              void* d_out, int out_size)
{
    const float* ci   = (const float*)d_in[0];
    const float* co   = (const float*)d_in[1];
    const float* ti   = (const float*)d_in[2];
    const float* ls   = (const float*)d_in[3];
    const float* W    = (const float*)d_in[4];
    const float* bias = (const float*)d_in[5];
    float* out = (float*)d_out;

    const int N = in_sizes[0] / BDIM;   // 2048
    const int M = in_sizes[2] / BDIM;   // 4096

    cudaFuncSetAttribute(k_all, cudaFuncAttributeMaxDynamicSharedMemorySize,
                         SM_FLOATS * 4);

    // two memset nodes total: lo_u := 0xFF..., everything else := 0
    void* p_ctrl;
    cudaGetSymbolAddress(&p_ctrl, g_ctrl);
    cudaMemsetAsync(p_ctrl, 0xFF, 4);
    cudaMemsetAsync((char*)p_ctrl + 4, 0x00, 35 * sizeof(unsigned));

    k_all<<<NBLK, NTHR, SM_FLOATS * 4>>>(ci, co, ti, ls, W, bias, out, N, M);
}